// round 4
// baseline (speedup 1.0000x reference)
#include <cuda_runtime.h>
#include <cstddef>

// Problem constants (fixed shapes): x = (256, 2048, 25, 3, 1) fp32
#define NB_ 256
#define TT 2048
#define NJ 25
#define ROW 75          // 25 joints * 3 channels, floats per frame
#define NI 57           // refined atomic intervals (all <= 48 frames)
#define NG 15           // gaussians per segment config
#define MAXF 48         // largest refined interval length in frames

// Refined union of gaussian chunk boundaries for nb_fr in {136, 68, 45} over
// T=2048, further split so every interval is <= 48 frames (load balance +
// small smem). Refinement is transparent to phase 2 (it just sums more terms).
__constant__ int c_bound[NI + 1] = {
       0,   45,   68,   90,  135,  136,  180,  204,  225,  270,
     272,  315,  340,  360,  405,  408,  450,  476,  495,  540,
     544,  585,  612,  630,  655,  680,  714,  748,  782,  816,
     850,  884,  918,  952,  998, 1043, 1088, 1134, 1179, 1224,
    1270, 1315, 1360, 1406, 1451, 1496, 1542, 1587, 1632, 1678,
    1723, 1768, 1814, 1859, 1904, 1952, 2000, 2048};

// Start interval index for each (u, g) gaussian: index i with c_bound[i] == g*nb.
__constant__ unsigned char c_start[45] = {
    // u=0 (nb=136)
    0, 5, 10, 15, 20, 25, 29, 33, 36, 39, 42, 45, 48, 51, 54,
    // u=1 (nb=68)
    0, 2, 5, 7, 10, 12, 15, 17, 20, 22, 25, 27, 29, 31, 33,
    // u=2 (nb=45)
    0, 1, 3, 4, 6, 8, 9, 11, 13, 14, 16, 18, 19, 21, 23};

// Phase-1 scratch: [b][interval][j*9 + e]  (13.1 MB)
__device__ float g_part[(size_t)NB_ * NI * (NJ * 9)];

// ---------------------------------------------------------------------------
// Phase 1: one block per (refined interval, batch). Coalesced stage of the
// interval's frames into shared (<= 14.4 KB -> 8 blocks/SM), per-(joint,
// lane-group) register accumulation of the 9 second-moment sums, warp-shuffle
// reduction over the 8-lane groups, coalesced store of the 225 partial sums.
// ---------------------------------------------------------------------------
__global__ __launch_bounds__(256) void k_partial(const float* __restrict__ x) {
    const int i   = blockIdx.x;     // interval
    const int b   = blockIdx.y;     // batch
    const int t0  = c_bound[i];
    const int F   = c_bound[i + 1] - t0;
    const int tid = threadIdx.x;

    __shared__ __align__(16) float sh[MAXF * ROW];     // 14.4 KB
    __shared__ float red[NJ * 9];

    const float* __restrict__ src = x + ((size_t)b * TT + t0) * ROW;
    const int n = F * ROW;
    for (int idx = tid; idx < n; idx += 256)
        sh[idx] = src[idx];
    __syncthreads();

    float a0 = 0.f, a1 = 0.f, a2 = 0.f, a3 = 0.f, a4 = 0.f,
          a5 = 0.f, a6 = 0.f, a7 = 0.f, a8 = 0.f;
    const int j   = tid >> 3;    // joint 0..31 (25 valid)
    const int grp = tid & 7;     // 8-lane frame group
    if (j < NJ) {
        const int base = j * 3;
        for (int f = grp; f < F; f += 8) {
            const float* p = sh + f * ROW + base;
            const float x0 = p[0], x1 = p[1], x2 = p[2];
            a0 += x0 * x0; a1 += x0 * x1; a2 += x0 * x2;
            a3 += x1 * x1; a4 += x1 * x2; a5 += x2 * x2;
            a6 += x0;      a7 += x1;      a8 += x2;
        }
    }
    #pragma unroll
    for (int d = 4; d >= 1; d >>= 1) {
        a0 += __shfl_down_sync(0xffffffffu, a0, d);
        a1 += __shfl_down_sync(0xffffffffu, a1, d);
        a2 += __shfl_down_sync(0xffffffffu, a2, d);
        a3 += __shfl_down_sync(0xffffffffu, a3, d);
        a4 += __shfl_down_sync(0xffffffffu, a4, d);
        a5 += __shfl_down_sync(0xffffffffu, a5, d);
        a6 += __shfl_down_sync(0xffffffffu, a6, d);
        a7 += __shfl_down_sync(0xffffffffu, a7, d);
        a8 += __shfl_down_sync(0xffffffffu, a8, d);
    }
    if (grp == 0 && j < NJ) {
        float* r = red + j * 9;
        r[0] = a0; r[1] = a1; r[2] = a2; r[3] = a3; r[4] = a4;
        r[5] = a5; r[6] = a6; r[7] = a7; r[8] = a8;
    }
    __syncthreads();
    if (tid < NJ * 9)
        g_part[((size_t)b * NI + i) * (NJ * 9) + tid] = red[tid];
}

// ---------------------------------------------------------------------------
// Phase 2: one block per (np, batch); the block owns all 5 p-joints of one
// joint-group np so output writes are fully contiguous float4 runs.
//   1) Load the 57x45 partials for this (b, np) into shared (coalesced).
//   2) 225 threads each combine one (p, seg-config, gaussian): sum intervals
//      (start index from constant table), scale by 1/N, assemble 4x4.
//   3) Write 1800 float4s: contiguous per (segment, np) — 4.8 KB runs.
// fin is declared FIRST and 16-aligned: the float4 reinterpret is legal.
// ---------------------------------------------------------------------------
__global__ __launch_bounds__(256) void k_final(float* __restrict__ out) {
    const int np  = blockIdx.x;   // joint-group 0..4
    const int b   = blockIdx.y;
    const int tid = threadIdx.x;

    __shared__ __align__(16) float fin[3 * NG * 5 * 16]; // 3600 floats: [u][g][p][16]
    __shared__ __align__(16) float s1[NI * 45];          // 2565 floats: [i][p*9+e]

    const float* __restrict__ base =
        g_part + (size_t)b * NI * (NJ * 9) + np * 45;
    for (int idx = tid; idx < NI * 45; idx += 256) {
        const int i = idx / 45;
        const int r = idx - i * 45;
        s1[idx] = base[(size_t)i * (NJ * 9) + r];
    }
    __syncthreads();

    if (tid < 225) {
        const int p = tid / 45;           // joint within group
        const int t = tid - p * 45;       // (u, g)
        const int u = t / 15;
        const int g = t - u * 15;
        const int nb = (u == 0) ? 136 : ((u == 1) ? 68 : 45);
        const int lo = g * nb;
        const int hi = (g == 14) ? TT : lo + nb;

        float s[9];
        #pragma unroll
        for (int e = 0; e < 9; ++e) s[e] = 0.f;
        for (int i = c_start[t]; c_bound[i] < hi; ++i) {
            const float* q = s1 + i * 45 + p * 9;
            #pragma unroll
            for (int e = 0; e < 9; ++e) s[e] += q[e];
        }
        const float invN = 1.0f / (float)(hi - lo);
        #pragma unroll
        for (int e = 0; e < 9; ++e) s[e] *= invN;

        float* f = fin + (t * 5 + p) * 16;
        f[0]  = s[0]; f[1]  = s[1]; f[2]  = s[2]; f[3]  = s[6];
        f[4]  = s[1]; f[5]  = s[3]; f[6]  = s[4]; f[7]  = s[7];
        f[8]  = s[2]; f[9]  = s[4]; f[10] = s[5]; f[11] = s[8];
        f[12] = s[6]; f[13] = s[7]; f[14] = s[8]; f[15] = 1.0f;
    }
    __syncthreads();

    // out shape: (b, 6, 5, 15, 5, 4, 4).  Per (b, sg, np): 300 float4s,
    // rem = g*20 + p*4 + q, matching fin's [u][g][p][q] float4 layout.
    float4* __restrict__ out4 = (float4*)out;
    const float4* __restrict__ f4 = (const float4*)fin;
    for (int vi = tid; vi < 6 * 300; vi += 256) {
        const int sg  = vi / 300;
        const int rem = vi - sg * 300;
        const int u   = (sg == 0) ? 0 : (sg < 3 ? 1 : 2);
        out4[((size_t)(b * 6 + sg) * 5 + np) * 300 + rem] = f4[u * 300 + rem];
    }
}

extern "C" void kernel_launch(void* const* d_in, const int* in_sizes, int n_in,
                              void* d_out, int out_size) {
    const float* x = (const float*)d_in[0];
    float* out = (float*)d_out;
    (void)in_sizes; (void)n_in; (void)out_size;

    k_partial<<<dim3(NI, NB_), 256>>>(x);
    k_final<<<dim3(5, NB_), 256>>>(out);
}

// round 8
// speedup vs baseline: 1.1763x; 1.1763x over previous
#include <cuda_runtime.h>
#include <cstddef>

// Problem constants (fixed shapes): x = (256, 2048, 25, 3, 1) fp32
#define NB_ 256
#define TT 2048
#define NJ 25
#define ROW 75          // 25 joints * 3 channels, floats per frame
#define NI 57           // refined atomic intervals (all <= 48 frames)
#define NG 15           // gaussians per segment config
#define MAXF 48         // largest refined interval length in frames

// Refined union of gaussian chunk boundaries for nb_fr in {136, 68, 45} over
// T=2048, further split so every interval is <= 48 frames.
__constant__ int c_bound[NI + 1] = {
       0,   45,   68,   90,  135,  136,  180,  204,  225,  270,
     272,  315,  340,  360,  405,  408,  450,  476,  495,  540,
     544,  585,  612,  630,  655,  680,  714,  748,  782,  816,
     850,  884,  918,  952,  998, 1043, 1088, 1134, 1179, 1224,
    1270, 1315, 1360, 1406, 1451, 1496, 1542, 1587, 1632, 1678,
    1723, 1768, 1814, 1859, 1904, 1952, 2000, 2048};

// c_slot[u][i] = gaussian slot whose START boundary is interval i (else -1).
__constant__ signed char c_slot[3][NI] = {
    // u=0 (nb=136): starts at i = 0,5,10,15,20,25,29,33,36,39,42,45,48,51,54
    { 0,-1,-1,-1,-1, 1,-1,-1,-1,-1, 2,-1,-1,-1,-1, 3,-1,-1,-1,-1,
      4,-1,-1,-1,-1, 5,-1,-1,-1, 6,-1,-1,-1, 7,-1,-1, 8,-1,-1, 9,
     -1,-1,10,-1,-1,11,-1,-1,12,-1,-1,13,-1,-1,14,-1,-1},
    // u=1 (nb=68): starts at i = 0,2,5,7,10,12,15,17,20,22,25,27,29,31,33
    { 0,-1, 1,-1,-1, 2,-1, 3,-1,-1, 4,-1, 5,-1,-1, 6,-1, 7,-1,-1,
      8,-1, 9,-1,-1,10,-1,11,-1,12,-1,13,-1,14,-1,-1,-1,-1,-1,-1,
     -1,-1,-1,-1,-1,-1,-1,-1,-1,-1,-1,-1,-1,-1,-1,-1,-1},
    // u=2 (nb=45): starts at i = 0,1,3,4,6,8,9,11,13,14,16,18,19,21,23
    { 0, 1,-1, 2, 3,-1, 4,-1, 5, 6,-1, 7,-1, 8, 9,-1,10,-1,11,12,
     -1,13,-1,14,-1,-1,-1,-1,-1,-1,-1,-1,-1,-1,-1,-1,-1,-1,-1,-1,
     -1,-1,-1,-1,-1,-1,-1,-1,-1,-1,-1,-1,-1,-1,-1,-1,-1}};

// 1/N for body gaussians (N = nb) and tail gaussian (N = T - 14*nb).
__constant__ float c_inv_nb[3]   = {1.0f / 136.0f, 1.0f / 68.0f,   1.0f / 45.0f};
__constant__ float c_inv_tail[3] = {1.0f / 144.0f, 1.0f / 1096.0f, 1.0f / 1418.0f};

// Phase-1 scratch: [b][interval][j*9 + e]  (13.1 MB)
__device__ float g_part[(size_t)NB_ * NI * (NJ * 9)];

// ---------------------------------------------------------------------------
// Phase 1: one block per (refined interval, batch). float4-vectorized stage
// of the interval's frames into shared (16B-aligned window, over/under-read
// stays inside the same batch), per-(joint, lane-group) register accumulation
// of the 9 second-moment sums, warp-shuffle reduction, coalesced store.
// ---------------------------------------------------------------------------
__global__ __launch_bounds__(256) void k_partial(const float* __restrict__ x) {
    const int i   = blockIdx.x;     // interval
    const int b   = blockIdx.y;     // batch
    const int t0  = c_bound[i];
    const int t1  = c_bound[i + 1];
    const int F   = t1 - t0;
    const int tid = threadIdx.x;

    __shared__ __align__(16) float sh[MAXF * ROW + 16];   // 14.5 KB
    __shared__ float red[NJ * 9];

    // Batch base is 614400 B (16B-aligned); widen [t0*ROW, t1*ROW) floats
    // down to a 16B-aligned start. Reads stay inside this batch's data.
    const size_t base   = (size_t)b * (TT * ROW);
    const int    s_elem = t0 * ROW;
    const int    s4     = s_elem & ~3;
    const int    pad    = s_elem & 3;
    const int    n4     = (t1 * ROW - s4 + 3) >> 2;

    const float4* __restrict__ g4 = (const float4*)(x + base + s4);
    float4* sh4 = (float4*)sh;
    #pragma unroll 4
    for (int idx = tid; idx < n4; idx += 256)
        sh4[idx] = g4[idx];
    __syncthreads();

    float a0 = 0.f, a1 = 0.f, a2 = 0.f, a3 = 0.f, a4 = 0.f,
          a5 = 0.f, a6 = 0.f, a7 = 0.f, a8 = 0.f;
    const int j   = tid >> 3;    // joint 0..31 (25 valid)
    const int grp = tid & 7;     // 8-lane frame group
    if (j < NJ) {
        const float* shp = sh + pad + j * 3;
        #pragma unroll 2
        for (int f = grp; f < F; f += 8) {
            const float* p = shp + f * ROW;
            const float x0 = p[0], x1 = p[1], x2 = p[2];
            a0 += x0 * x0; a1 += x0 * x1; a2 += x0 * x2;
            a3 += x1 * x1; a4 += x1 * x2; a5 += x2 * x2;
            a6 += x0;      a7 += x1;      a8 += x2;
        }
    }
    #pragma unroll
    for (int d = 4; d >= 1; d >>= 1) {
        a0 += __shfl_down_sync(0xffffffffu, a0, d);
        a1 += __shfl_down_sync(0xffffffffu, a1, d);
        a2 += __shfl_down_sync(0xffffffffu, a2, d);
        a3 += __shfl_down_sync(0xffffffffu, a3, d);
        a4 += __shfl_down_sync(0xffffffffu, a4, d);
        a5 += __shfl_down_sync(0xffffffffu, a5, d);
        a6 += __shfl_down_sync(0xffffffffu, a6, d);
        a7 += __shfl_down_sync(0xffffffffu, a7, d);
        a8 += __shfl_down_sync(0xffffffffu, a8, d);
    }
    if (grp == 0 && j < NJ) {
        float* r = red + j * 9;
        r[0] = a0; r[1] = a1; r[2] = a2; r[3] = a3; r[4] = a4;
        r[5] = a5; r[6] = a6; r[7] = a7; r[8] = a8;
    }
    __syncthreads();
    if (tid < NJ * 9)
        g_part[((size_t)b * NI + i) * (NJ * 9) + tid] = red[tid];
}

// ---------------------------------------------------------------------------
// Phase 2: one block per (sg, batch). 225 channel-threads build a prefix sum
// over the 57 intervals (fully unrolled: 57 independent LDGs in flight, FADD
// chain only), storing the prefix ONLY at the 16 gaussian boundaries of this
// segment's u config. Each gaussian moment is then P[g+1]-P[g] (O(1)).
// Assemble 4x4 matrices into a 24 KB tile, stream out contiguously as float4.
// ---------------------------------------------------------------------------
__global__ __launch_bounds__(256) void k_out(float* __restrict__ out) {
    const int sg  = blockIdx.x;   // segment 0..5
    const int b   = blockIdx.y;
    const int tid = threadIdx.x;
    const int u   = (sg == 0) ? 0 : (sg < 3 ? 1 : 2);

    __shared__ __align__(16) float sP[16 * 225];          // 14.4 KB prefixes
    __shared__ __align__(16) float fin[375 * 16];         // 24 KB matrices

    // Exclusive prefix over intervals, sampled at this u's gaussian starts.
    if (tid < NJ * 9) {
        const float* __restrict__ gp =
            g_part + (size_t)b * NI * (NJ * 9) + tid;
        float run = 0.f;
        #pragma unroll
        for (int i = 0; i < NI; ++i) {
            const int sl = c_slot[u][i];
            if (sl >= 0) sP[sl * 225 + tid] = run;
            run += gp[(size_t)i * (NJ * 9)];
        }
        sP[15 * 225 + tid] = run;   // total (end boundary of tail gaussian)
    }
    __syncthreads();

    // 375 outputs per block: o = np*75 + g*5 + p  (matches out layout).
    for (int o = tid; o < 375; o += 256) {
        const int np = o / 75;
        const int r  = o - np * 75;
        const int g  = r / 5;
        const int p  = r - g * 5;
        const int j9 = (np * 5 + p) * 9;
        const float invN = (g < 14) ? c_inv_nb[u] : c_inv_tail[u];

        const float* Pa = sP + g * 225 + j9;
        const float* Pb = Pa + 225;
        float s[9];
        #pragma unroll
        for (int e = 0; e < 9; ++e)
            s[e] = (Pb[e] - Pa[e]) * invN;

        float* f = fin + o * 16;
        f[0]  = s[0]; f[1]  = s[1]; f[2]  = s[2]; f[3]  = s[6];
        f[4]  = s[1]; f[5]  = s[3]; f[6]  = s[4]; f[7]  = s[7];
        f[8]  = s[2]; f[9]  = s[4]; f[10] = s[5]; f[11] = s[8];
        f[12] = s[6]; f[13] = s[7]; f[14] = s[8]; f[15] = 1.0f;
    }
    __syncthreads();

    // out shape (b, 6, 5, 15, 5, 4, 4): per (b, sg) a contiguous 24 KB run of
    // 1500 float4 in exactly fin's (np, g, p, 16) order.
    float4* __restrict__ out4 =
        (float4*)out + (size_t)(b * 6 + sg) * 1500;
    const float4* __restrict__ f4 = (const float4*)fin;
    #pragma unroll 2
    for (int vi = tid; vi < 1500; vi += 256)
        out4[vi] = f4[vi];
}

extern "C" void kernel_launch(void* const* d_in, const int* in_sizes, int n_in,
                              void* d_out, int out_size) {
    const float* x = (const float*)d_in[0];
    float* out = (float*)d_out;
    (void)in_sizes; (void)n_in; (void)out_size;

    k_partial<<<dim3(NI, NB_), 256>>>(x);
    k_out<<<dim3(6, NB_), 256>>>(out);
}

// round 10
// speedup vs baseline: 1.2106x; 1.0291x over previous
#include <cuda_runtime.h>
#include <cstddef>
#include <cstdint>

// Problem constants (fixed shapes): x = (256, 2048, 25, 3, 1) fp32
#define NB_ 256
#define TT 2048
#define NJ 25
#define ROW 75          // 25 joints * 3 channels, floats per frame
#define NI 57           // refined atomic intervals (all <= 48 frames)
#define NG 15           // gaussians per segment config
#define MAXF 48         // largest refined interval length in frames
#define BUFN (MAXF * ROW + 4)   // 3604 floats per stage buffer

// Refined union of gaussian chunk boundaries for nb_fr in {136, 68, 45} over
// T=2048, further split so every interval is <= 48 frames.
__constant__ int c_bound[NI + 1] = {
       0,   45,   68,   90,  135,  136,  180,  204,  225,  270,
     272,  315,  340,  360,  405,  408,  450,  476,  495,  540,
     544,  585,  612,  630,  655,  680,  714,  748,  782,  816,
     850,  884,  918,  952,  998, 1043, 1088, 1134, 1179, 1224,
    1270, 1315, 1360, 1406, 1451, 1496, 1542, 1587, 1632, 1678,
    1723, 1768, 1814, 1859, 1904, 1952, 2000, 2048};

// Interval-index splits giving 4 balanced runs (540/503/499/506 frames).
__constant__ int c_qsplit[5] = {0, 19, 35, 46, 57};

// c_slot[u][i] = gaussian slot whose START boundary is interval i (else -1).
__constant__ signed char c_slot[3][NI] = {
    { 0,-1,-1,-1,-1, 1,-1,-1,-1,-1, 2,-1,-1,-1,-1, 3,-1,-1,-1,-1,
      4,-1,-1,-1,-1, 5,-1,-1,-1, 6,-1,-1,-1, 7,-1,-1, 8,-1,-1, 9,
     -1,-1,10,-1,-1,11,-1,-1,12,-1,-1,13,-1,-1,14,-1,-1},
    { 0,-1, 1,-1,-1, 2,-1, 3,-1,-1, 4,-1, 5,-1,-1, 6,-1, 7,-1,-1,
      8,-1, 9,-1,-1,10,-1,11,-1,12,-1,13,-1,14,-1,-1,-1,-1,-1,-1,
     -1,-1,-1,-1,-1,-1,-1,-1,-1,-1,-1,-1,-1,-1,-1,-1,-1},
    { 0, 1,-1, 2, 3,-1, 4,-1, 5, 6,-1, 7,-1, 8, 9,-1,10,-1,11,12,
     -1,13,-1,14,-1,-1,-1,-1,-1,-1,-1,-1,-1,-1,-1,-1,-1,-1,-1,-1,
     -1,-1,-1,-1,-1,-1,-1,-1,-1,-1,-1,-1,-1,-1,-1,-1,-1}};

// 1/N for body gaussians (N = nb) and tail gaussian (N = T - 14*nb).
__constant__ float c_inv_nb[3]   = {1.0f / 136.0f, 1.0f / 68.0f,   1.0f / 45.0f};
__constant__ float c_inv_tail[3] = {1.0f / 144.0f, 1.0f / 1096.0f, 1.0f / 1418.0f};

// Row entry index tables for the 4x4 augmented matrix rows (q = row).
// Row 3's last entry is the constant 1.0 (handled specially).
__constant__ int c_tab[4][4] = {
    {0, 1, 2, 6}, {1, 3, 4, 7}, {2, 4, 5, 8}, {6, 7, 8, 8}};

// Phase-1 scratch: [b][interval][j*9 + e]  (13.1 MB)
__device__ float g_part[(size_t)NB_ * NI * (NJ * 9)];

// ---------------------------------------------------------------------------
// Phase 1: one block per (interval-run, batch) -> 1024 blocks = ONE wave.
// Each block walks its ~14 intervals with cp.async double-buffered staging:
// interval i+1 streams global->shared while interval i is reduced. Per
// interval: per-(joint, lane-group) register accumulation of the 9
// second-moment sums, warp-shuffle reduction, coalesced 225-float store.
// ---------------------------------------------------------------------------
__global__ __launch_bounds__(256) void k_partial(const float* __restrict__ x) {
    const int qg  = blockIdx.x;     // interval-run 0..3
    const int b   = blockIdx.y;     // batch
    const int i0  = c_qsplit[qg];
    const int i1  = c_qsplit[qg + 1];
    const int tid = threadIdx.x;

    __shared__ __align__(16) float sh[2][BUFN];   // 28.8 KB double buffer
    __shared__ float red[NJ * 9];

    const size_t base = (size_t)b * (TT * ROW);   // 16B-aligned per batch

    // Stage interval i into buffer s via cp.async 16B (register-bypass).
    // Window widened down to a 16B boundary; over-read stays in this batch.
    auto stage = [&](int i, int s) {
        const int t0 = c_bound[i], t1 = c_bound[i + 1];
        const int s4 = (t0 * ROW) & ~3;
        const int n4 = (t1 * ROW - s4 + 3) >> 2;
        const float* __restrict__ g = x + base + s4;
        uint32_t sm = (uint32_t)__cvta_generic_to_shared(sh[s]);
        for (int idx = tid; idx < n4; idx += 256) {
            asm volatile("cp.async.cg.shared.global [%0], [%1], 16;"
                         :: "r"(sm + idx * 16), "l"(g + idx * 4) : "memory");
        }
        asm volatile("cp.async.commit_group;" ::: "memory");
    };

    stage(i0, 0);
    for (int i = i0; i < i1; ++i) {
        const int s = (i - i0) & 1;
        if (i + 1 < i1) {
            stage(i + 1, s ^ 1);
            asm volatile("cp.async.wait_group 1;" ::: "memory");
        } else {
            asm volatile("cp.async.wait_group 0;" ::: "memory");
        }
        __syncthreads();

        const int t0  = c_bound[i];
        const int F   = c_bound[i + 1] - t0;
        const int pad = (t0 * ROW) & 3;

        float a0 = 0.f, a1 = 0.f, a2 = 0.f, a3 = 0.f, a4 = 0.f,
              a5 = 0.f, a6 = 0.f, a7 = 0.f, a8 = 0.f;
        const int j   = tid >> 3;    // joint 0..31 (25 valid)
        const int grp = tid & 7;     // 8-lane frame group
        if (j < NJ) {
            const float* shp = sh[s] + pad + j * 3;
            #pragma unroll 2
            for (int f = grp; f < F; f += 8) {
                const float* p = shp + f * ROW;
                const float x0 = p[0], x1 = p[1], x2 = p[2];
                a0 += x0 * x0; a1 += x0 * x1; a2 += x0 * x2;
                a3 += x1 * x1; a4 += x1 * x2; a5 += x2 * x2;
                a6 += x0;      a7 += x1;      a8 += x2;
            }
        }
        #pragma unroll
        for (int d = 4; d >= 1; d >>= 1) {
            a0 += __shfl_down_sync(0xffffffffu, a0, d);
            a1 += __shfl_down_sync(0xffffffffu, a1, d);
            a2 += __shfl_down_sync(0xffffffffu, a2, d);
            a3 += __shfl_down_sync(0xffffffffu, a3, d);
            a4 += __shfl_down_sync(0xffffffffu, a4, d);
            a5 += __shfl_down_sync(0xffffffffu, a5, d);
            a6 += __shfl_down_sync(0xffffffffu, a6, d);
            a7 += __shfl_down_sync(0xffffffffu, a7, d);
            a8 += __shfl_down_sync(0xffffffffu, a8, d);
        }
        if (grp == 0 && j < NJ) {
            float* r = red + j * 9;
            r[0] = a0; r[1] = a1; r[2] = a2; r[3] = a3; r[4] = a4;
            r[5] = a5; r[6] = a6; r[7] = a7; r[8] = a8;
        }
        __syncthreads();
        if (tid < NJ * 9)
            g_part[((size_t)b * NI + i) * (NJ * 9) + tid] = red[tid];
        __syncthreads();   // buffer s reused by stage(i+2); red reused next i
    }
}

// ---------------------------------------------------------------------------
// Phase 2: one block per (sg, batch). 225 channel-threads build a prefix sum
// over the 57 intervals (fully unrolled: independent LDGs, FADD chain only),
// sampling the prefix at the 16 gaussian boundaries of this segment's config.
// Each output float4 (one matrix row) is then computed directly from two
// prefix samples and stored with a coalesced STG.128 — no fin tile, no bank
// conflicts, smem only 14.4 KB.
// ---------------------------------------------------------------------------
__global__ __launch_bounds__(256) void k_out(float* __restrict__ out) {
    const int sg  = blockIdx.x;   // segment 0..5
    const int b   = blockIdx.y;
    const int tid = threadIdx.x;
    const int u   = (sg == 0) ? 0 : (sg < 3 ? 1 : 2);

    __shared__ __align__(16) float sP[16 * 225];   // 14.4 KB prefixes

    if (tid < NJ * 9) {
        const float* __restrict__ gp =
            g_part + (size_t)b * NI * (NJ * 9) + tid;
        float run = 0.f;
        #pragma unroll
        for (int i = 0; i < NI; ++i) {
            const int sl = c_slot[u][i];
            if (sl >= 0) sP[sl * 225 + tid] = run;
            run += gp[(size_t)i * (NJ * 9)];
        }
        sP[15 * 225 + tid] = run;   // end boundary of the tail gaussian
    }
    __syncthreads();

    // 1500 float4 rows per block: vi = o*4 + q, o = np*75 + g*5 + p (output
    // order), q = matrix row. Fully coalesced 2KB-per-warp STG.128 runs.
    float4* __restrict__ out4 = (float4*)out + (size_t)(b * 6 + sg) * 1500;
    for (int vi = tid; vi < 1500; vi += 256) {
        const int o  = vi >> 2;
        const int q  = vi & 3;
        const int np = o / 75;
        const int r  = o - np * 75;
        const int g  = r / 5;
        const int p  = r - g * 5;
        const int j9 = (np * 5 + p) * 9;
        const float invN = (g < 14) ? c_inv_nb[u] : c_inv_tail[u];

        const float* Pa = sP + g * 225 + j9;
        const float* Pb = Pa + 225;
        const int* e = c_tab[q];
        float4 v;
        v.x = (Pb[e[0]] - Pa[e[0]]) * invN;
        v.y = (Pb[e[1]] - Pa[e[1]]) * invN;
        v.z = (Pb[e[2]] - Pa[e[2]]) * invN;
        v.w = (q == 3) ? 1.0f : (Pb[e[3]] - Pa[e[3]]) * invN;
        out4[vi] = v;
    }
}

extern "C" void kernel_launch(void* const* d_in, const int* in_sizes, int n_in,
                              void* d_out, int out_size) {
    const float* x = (const float*)d_in[0];
    float* out = (float*)d_out;
    (void)in_sizes; (void)n_in; (void)out_size;

    k_partial<<<dim3(4, NB_), 256>>>(x);
    k_out<<<dim3(6, NB_), 256>>>(out);
}

// round 11
// speedup vs baseline: 1.2897x; 1.0654x over previous
#include <cuda_runtime.h>
#include <cstddef>
#include <cstdint>

// Problem constants (fixed shapes): x = (256, 2048, 25, 3, 1) fp32
#define NB_ 256
#define TT 2048
#define NJ 25
#define ROW 75          // 25 joints * 3 channels, floats per frame
#define NI 57           // refined atomic intervals (all <= 48 frames)
#define MAXF 48         // largest refined interval length in frames
#define BUFN (MAXF * ROW + 4)   // 3604 floats per stage buffer
#define NSL 37          // distinct sampled prefix slots (union of boundaries)

// Refined union of gaussian chunk boundaries for nb_fr in {136, 68, 45} over
// T=2048, further split so every interval is <= 48 frames.
__constant__ int c_bound[NI + 1] = {
       0,   45,   68,   90,  135,  136,  180,  204,  225,  270,
     272,  315,  340,  360,  405,  408,  450,  476,  495,  540,
     544,  585,  612,  630,  655,  680,  714,  748,  782,  816,
     850,  884,  918,  952,  998, 1043, 1088, 1134, 1179, 1224,
    1270, 1315, 1360, 1406, 1451, 1496, 1542, 1587, 1632, 1678,
    1723, 1768, 1814, 1859, 1904, 1952, 2000, 2048};

// Interval-index splits giving 4 balanced runs (540/503/499/506 frames).
__constant__ int c_qsplit[5] = {0, 19, 35, 46, 57};

// c_samp[i] = sample slot of boundary index i (prefix BEFORE interval i), or -1.
__constant__ signed char c_samp[NI + 1] = {
     0,  1,  2,  3,  4,  5,  6,  7,  8,  9, 10, 11, 12, 13, 14, 15,
    16, 17, 18, 19, 20, 21, 22, 23, -1, 24, -1, 25, -1, 26, -1, 27,
    -1, 28, -1, -1, 29, -1, -1, 30, -1, -1, 31, -1, -1, 32, -1, -1,
    33, -1, -1, 34, -1, -1, 35, -1, -1, 36};

// Per (u*15+g): sample slot of gaussian start / end boundary.
__constant__ unsigned char c_sslot[45] = {
    0, 5,10,15,20,24,26,28,29,30,31,32,33,34,35,      // u=0 (nb=136)
    0, 2, 5, 7,10,12,15,17,20,22,24,25,26,27,28,      // u=1 (nb=68)
    0, 1, 3, 4, 6, 8, 9,11,13,14,16,18,19,21,23};     // u=2 (nb=45)
__constant__ unsigned char c_eslot[45] = {
    5,10,15,20,24,26,28,29,30,31,32,33,34,35,36,
    2, 5, 7,10,12,15,17,20,22,24,25,26,27,28,36,
    1, 3, 4, 6, 8, 9,11,13,14,16,18,19,21,23,36};

// 1/N for body gaussians (N = nb) and tail gaussian (N = T - 14*nb).
__constant__ float c_inv_nb[3]   = {1.0f / 136.0f, 1.0f / 68.0f,   1.0f / 45.0f};
__constant__ float c_inv_tail[3] = {1.0f / 144.0f, 1.0f / 1096.0f, 1.0f / 1418.0f};

// Row entry index tables for the 4x4 augmented matrix rows (q = row).
// Row 3's last entry is the constant 1.0 (handled specially).
__constant__ int c_tab[4][4] = {
    {0, 1, 2, 6}, {1, 3, 4, 7}, {2, 4, 5, 8}, {6, 7, 8, 8}};

// Phase-1 scratch: [b][interval][j*9 + e]  (13.1 MB)
__device__ float g_part[(size_t)NB_ * NI * (NJ * 9)];

// ---------------------------------------------------------------------------
// Phase 1: one block per (interval-run, batch) -> 1024 blocks = ONE wave.
// cp.async double-buffered staging; inner loop uses PACKED fp32x2 FMA
// (fma.rn.f32x2, PTX-only) to halve fma-pipe issue: per frame only
// 3xFFMA2 + 1xADD2 + 1xFADD instead of 12 scalar fma-pipe ops.
// Accumulator packing: A01=(a0,a1) A24=(a2,a4) A35=(a3,a5) A67=(a6,a7), a8.
// ---------------------------------------------------------------------------
__global__ __launch_bounds__(256) void k_partial(const float* __restrict__ x) {
    const int qg  = blockIdx.x;     // interval-run 0..3
    const int b   = blockIdx.y;     // batch
    const int i0  = c_qsplit[qg];
    const int i1  = c_qsplit[qg + 1];
    const int tid = threadIdx.x;

    __shared__ __align__(16) float sh[2][BUFN];   // 28.8 KB double buffer
    __shared__ float red[NJ * 9];

    const size_t base = (size_t)b * (TT * ROW);   // 16B-aligned per batch

    auto stage = [&](int i, int s) {
        const int t0 = c_bound[i], t1 = c_bound[i + 1];
        const int s4 = (t0 * ROW) & ~3;
        const int n4 = (t1 * ROW - s4 + 3) >> 2;
        const float* __restrict__ g = x + base + s4;
        uint32_t sm = (uint32_t)__cvta_generic_to_shared(sh[s]);
        for (int idx = tid; idx < n4; idx += 256) {
            asm volatile("cp.async.cg.shared.global [%0], [%1], 16;"
                         :: "r"(sm + idx * 16), "l"(g + idx * 4) : "memory");
        }
        asm volatile("cp.async.commit_group;" ::: "memory");
    };

    stage(i0, 0);
    for (int i = i0; i < i1; ++i) {
        const int s = (i - i0) & 1;
        if (i + 1 < i1) {
            stage(i + 1, s ^ 1);
            asm volatile("cp.async.wait_group 1;" ::: "memory");
        } else {
            asm volatile("cp.async.wait_group 0;" ::: "memory");
        }
        __syncthreads();

        const int t0  = c_bound[i];
        const int F   = c_bound[i + 1] - t0;
        const int pad = (t0 * ROW) & 3;

        unsigned long long A01 = 0ull, A24 = 0ull, A35 = 0ull, A67 = 0ull;
        float a8 = 0.f;
        const int j   = tid >> 3;    // joint 0..31 (25 valid)
        const int grp = tid & 7;     // 8-lane frame group
        if (j < NJ) {
            const float* shp = sh[s] + pad + j * 3;
            #pragma unroll 2
            for (int f = grp; f < F; f += 8) {
                const float* p = shp + f * ROW;
                const float x0 = p[0], x1 = p[1], x2 = p[2];
                unsigned long long P01, P00, P22, P12;
                asm("mov.b64 %0,{%1,%2};" : "=l"(P01) : "f"(x0), "f"(x1));
                asm("mov.b64 %0,{%1,%2};" : "=l"(P00) : "f"(x0), "f"(x0));
                asm("mov.b64 %0,{%1,%2};" : "=l"(P22) : "f"(x2), "f"(x2));
                asm("mov.b64 %0,{%1,%2};" : "=l"(P12) : "f"(x1), "f"(x2));
                asm("fma.rn.f32x2 %0,%1,%2,%0;" : "+l"(A01) : "l"(P00), "l"(P01));
                asm("fma.rn.f32x2 %0,%1,%2,%0;" : "+l"(A24) : "l"(P22), "l"(P01));
                asm("fma.rn.f32x2 %0,%1,%2,%0;" : "+l"(A35) : "l"(P12), "l"(P12));
                asm("add.rn.f32x2 %0,%0,%1;"    : "+l"(A67) : "l"(P01));
                a8 += x2;
            }
        }
        float a0, a1, a2, a3, a4, a5, a6, a7;
        asm("mov.b64 {%0,%1},%2;" : "=f"(a0), "=f"(a1) : "l"(A01));
        asm("mov.b64 {%0,%1},%2;" : "=f"(a2), "=f"(a4) : "l"(A24));
        asm("mov.b64 {%0,%1},%2;" : "=f"(a3), "=f"(a5) : "l"(A35));
        asm("mov.b64 {%0,%1},%2;" : "=f"(a6), "=f"(a7) : "l"(A67));

        #pragma unroll
        for (int d = 4; d >= 1; d >>= 1) {
            a0 += __shfl_down_sync(0xffffffffu, a0, d);
            a1 += __shfl_down_sync(0xffffffffu, a1, d);
            a2 += __shfl_down_sync(0xffffffffu, a2, d);
            a3 += __shfl_down_sync(0xffffffffu, a3, d);
            a4 += __shfl_down_sync(0xffffffffu, a4, d);
            a5 += __shfl_down_sync(0xffffffffu, a5, d);
            a6 += __shfl_down_sync(0xffffffffu, a6, d);
            a7 += __shfl_down_sync(0xffffffffu, a7, d);
            a8 += __shfl_down_sync(0xffffffffu, a8, d);
        }
        if (grp == 0 && j < NJ) {
            float* r = red + j * 9;
            r[0] = a0; r[1] = a1; r[2] = a2; r[3] = a3; r[4] = a4;
            r[5] = a5; r[6] = a6; r[7] = a7; r[8] = a8;
        }
        __syncthreads();
        if (tid < NJ * 9)
            g_part[((size_t)b * NI + i) * (NJ * 9) + tid] = red[tid];
        __syncthreads();   // buffer s reused by stage(i+2); red reused next i
    }
}

// ---------------------------------------------------------------------------
// Phase 2: ONE block per batch (256 blocks x 512 thr). The interval prefix is
// computed ONCE (225 channel-threads, 57 unrolled L2 loads), sampled into the
// 37-slot union of all gaussian boundaries (33.3 KB smem). Then all 6
// segments' 9000 float4 rows are produced directly from prefix differences
// with coalesced STG.128 — 6x fewer g_part reads and 6x less prefix work
// than the per-(sg,b) version.
// ---------------------------------------------------------------------------
__global__ __launch_bounds__(512) void k_out(float* __restrict__ out) {
    const int b   = blockIdx.x;
    const int tid = threadIdx.x;

    __shared__ __align__(16) float sP[NSL * 225];   // 33.3 KB sampled prefixes

    if (tid < NJ * 9) {
        const float* __restrict__ gp =
            g_part + (size_t)b * NI * (NJ * 9) + tid;
        float run = 0.f;
        #pragma unroll
        for (int i = 0; i < NI; ++i) {
            const int sl = c_samp[i];
            if (sl >= 0) sP[sl * 225 + tid] = run;
            run += gp[(size_t)i * (NJ * 9)];
        }
        sP[(NSL - 1) * 225 + tid] = run;   // boundary 57 (slot 36)
    }
    __syncthreads();

    // 9000 float4 rows for this batch: vi = sg*1500 + o*4 + q,
    // o = np*75 + g*5 + p (output order), q = matrix row.
    float4* __restrict__ out4 = (float4*)out + (size_t)b * 9000;
    for (int vi = tid; vi < 9000; vi += 512) {
        const int sg  = vi / 1500;
        const int rem = vi - sg * 1500;
        const int o   = rem >> 2;
        const int q   = rem & 3;
        const int np  = o / 75;
        const int r   = o - np * 75;
        const int g   = r / 5;
        const int p   = r - g * 5;
        const int u   = (sg == 0) ? 0 : (sg < 3 ? 1 : 2);
        const int t   = u * 15 + g;
        const int j9  = (np * 5 + p) * 9;
        const float invN = (g < 14) ? c_inv_nb[u] : c_inv_tail[u];

        const float* Pa = sP + (int)c_sslot[t] * 225 + j9;
        const float* Pb = sP + (int)c_eslot[t] * 225 + j9;
        const int* e = c_tab[q];
        float4 v;
        v.x = (Pb[e[0]] - Pa[e[0]]) * invN;
        v.y = (Pb[e[1]] - Pa[e[1]]) * invN;
        v.z = (Pb[e[2]] - Pa[e[2]]) * invN;
        v.w = (q == 3) ? 1.0f : (Pb[e[3]] - Pa[e[3]]) * invN;
        out4[vi] = v;
    }
}

extern "C" void kernel_launch(void* const* d_in, const int* in_sizes, int n_in,
                              void* d_out, int out_size) {
    const float* x = (const float*)d_in[0];
    float* out = (float*)d_out;
    (void)in_sizes; (void)n_in; (void)out_size;

    k_partial<<<dim3(4, NB_), 256>>>(x);
    k_out<<<NB_, 512>>>(out);
}